// round 10
// baseline (speedup 1.0000x reference)
#include <cuda_runtime.h>
#include <cuda_bf16.h>
#include <cstdint>

#define N_NODES 8192
#define F_DIM   256
#define H_DIM   64
#define NS      80      // padded B rows: 64 h-feats + 1 ones (deg) + 15 zero
#define KSPLIT  4
#define MT      64      // M rows per CTA (4 warps x 16)
#define KC      32      // K chunk (halved: enables A double-buffer at same reg count)

// ---------------- scratch (static device globals; no allocation) ----------------
__device__ __align__(16) float          d_WtT[F_DIM * H_DIM];       // [256][64]
__device__ __align__(16) float          d_WpT[H_DIM * F_DIM];       // [64][256]
__device__ __align__(16) __nv_bfloat16  d_hT[NS * N_NODES];         // [80][8192]
__device__ __align__(16) float          d_part[(size_t)KSPLIT * N_NODES * NS]; // ~10.5MB
__device__ __align__(16) float          d_hsum[H_DIM];

// ---------------- K0: transpose weights, fill padded hT rows ----------------
__global__ void k0_prep(const float* __restrict__ Wt, const float* __restrict__ Wp) {
    int i = blockIdx.x * blockDim.x + threadIdx.x;
    if (i < 16384) {
        int f = i >> 6, t = i & 63;
        d_WtT[i] = Wt[t * 256 + f];
    } else if (i < 32768) {
        int j = i - 16384;
        int t = j >> 8, f = j & 255;
        d_WpT[j] = Wp[f * 64 + t];
    } else if (i < 32768 + 16 * 8192) {
        int j = i - 32768;
        int r = j >> 13, c = j & 8191;              // rows 64..79
        d_hT[(64 + r) * 8192 + c] = (r == 0) ? __float2bfloat16(1.0f)
                                             : __float2bfloat16(0.0f);
    }
}

// ---------------- K1: h = x@Wt^T + bt, write transposed bf16 hT[t][node] ----------------
__global__ __launch_bounds__(256) void k1_feat(const float* __restrict__ x,
                                               const float* __restrict__ bt) {
    __shared__ float xs[64 * 65];
    __shared__ float ws[64 * 64];
    int tid = threadIdx.x;
    int i0  = blockIdx.x * 64;
    int t   = tid & 63, grp = tid >> 6;
    float acc[16];
#pragma unroll
    for (int j = 0; j < 16; ++j) acc[j] = 0.f;

    for (int c = 0; c < 4; ++c) {
        __syncthreads();
#pragma unroll
        for (int it = 0; it < 16; ++it) {
            int idx = it * 256 + tid;
            int n = idx >> 6, f = idx & 63;
            xs[n * 65 + f] = x[(size_t)(i0 + n) * 256 + c * 64 + f];
            ws[idx]        = d_WtT[c * 4096 + idx];
        }
        __syncthreads();
#pragma unroll 8
        for (int f = 0; f < 64; ++f) {
            float wv = ws[f * 64 + t];
#pragma unroll
            for (int j = 0; j < 16; ++j)
                acc[j] += xs[(grp * 16 + j) * 65 + f] * wv;
        }
    }
    float bv = bt[t];
#pragma unroll
    for (int j = 0; j < 16; ++j) {
        int node = i0 + grp * 16 + j;
        d_hT[t * 8192 + node] = __float2bfloat16(acc[j] + bv);
    }
}

// ---------------- K1b: column sums of h (deg==0 fallback) ----------------
__global__ void k1b_hsum() {
    int t = blockIdx.x, tid = threadIdx.x;
    float s = 0.f;
    for (int i = tid; i < 8192; i += 256)
        s += __bfloat162float(d_hT[t * 8192 + i]);
#pragma unroll
    for (int off = 16; off; off >>= 1) s += __shfl_xor_sync(0xffffffffu, s, off);
    __shared__ float red[8];
    if ((tid & 31) == 0) red[tid >> 5] = s;
    __syncthreads();
    if (tid == 0) {
        float tot = 0.f;
        for (int w = 0; w < 8; ++w) tot += red[w];
        d_hsum[t] = tot;
    }
}

// ---------------- K2: SpMM, software-pipelined adj stream + mma ----------------
__device__ __forceinline__ void cp16(unsigned dst, const void* src) {
    asm volatile("cp.async.cg.shared.global [%0], [%1], 16;\n" :: "r"(dst), "l"(src));
}
__device__ __forceinline__ unsigned cvt01(int lo, int hi) {
    // {0,1} ints -> packed bf16x2 {0, 1.0f}
    return (unsigned)lo * 0x3F80u + (unsigned)hi * 0x3F800000u;
}

__global__ __launch_bounds__(128, 4) void k2_spmm(const int* __restrict__ adj) {
    // B stage: 80 rows x 32 k (64B/row), XOR swizzle u^=(r>>1)&3 (conflict-free)
    __shared__ __align__(16) unsigned char Bs[2][NS * 64];
    int tid  = threadIdx.x;
    int lane = tid & 31, mw = tid >> 5;
    int i0    = blockIdx.x * MT;
    int ks    = blockIdx.y;
    int kbase = ks * (N_NODES / KSPLIT);
    const int NCH = (N_NODES / KSPLIT) / KC;   // 64

    float c[10][4];
#pragma unroll
    for (int nf = 0; nf < 10; ++nf)
#pragma unroll
        for (int q = 0; q < 4; ++q) c[nf][q] = 0.f;

    // B prefetch: 320 16B units per stage
#define PREFETCH_B(stage, kc0)                                                        \
    {                                                                                 \
        _Pragma("unroll")                                                             \
        for (int i = 0; i < 3; ++i) {                                                 \
            int idx = tid + i * 128;                                                  \
            if (idx < 320) {                                                          \
                int r = idx >> 2, u = idx & 3;                                        \
                const unsigned char* src = (const unsigned char*)d_hT +               \
                    (size_t)r * (N_NODES * 2) + (size_t)(kc0) * 2 + u * 16;           \
                unsigned dst = (unsigned)__cvta_generic_to_shared(                    \
                    &Bs[stage][r * 64 + ((u ^ ((r >> 1) & 3)) * 16)]);                \
                cp16(dst, src);                                                       \
            }                                                                         \
        }                                                                             \
        asm volatile("cp.async.commit_group;\n");                                     \
    }

    int g = lane >> 2, tg = lane & 3;
    int rowA = i0 + mw * 16 + g;
    const int* aptr0 = adj + (size_t)rowA * N_NODES + kbase + tg * 2;
    const int* aptr1 = aptr0 + (size_t)8 * N_NODES;

    int2 araw[2][2][2][2];   // [stage][kk][rowsel][khalf]

#define LOAD_A(stage, coff)                                                           \
    {                                                                                 \
        _Pragma("unroll")                                                             \
        for (int kk = 0; kk < 2; ++kk)                                                \
        {                                                                             \
            _Pragma("unroll")                                                         \
            for (int h = 0; h < 2; ++h) {                                             \
                araw[stage][kk][0][h] = *(const int2*)(aptr0 + (coff) + kk * 16 + h * 8); \
                araw[stage][kk][1][h] = *(const int2*)(aptr1 + (coff) + kk * 16 + h * 8); \
            }                                                                         \
        }                                                                             \
    }

    PREFETCH_B(0, kbase);
    LOAD_A(0, 0);
    PREFETCH_B(1, kbase + KC);

    for (int ch = 0; ch < NCH; ++ch) {
        int cur = ch & 1;
        if (ch + 1 < NCH) {
            asm volatile("cp.async.wait_group 1;\n");
        } else {
            asm volatile("cp.async.wait_group 0;\n");
        }
        __syncthreads();
        // issue next chunk's adjacency loads BEFORE consuming this chunk:
        // keeps the DRAM stream busy during ldmatrix/mma
        if (ch + 1 < NCH) LOAD_A(cur ^ 1, (ch + 1) * KC);

#pragma unroll
        for (int kk = 0; kk < 2; ++kk) {
            unsigned a0 = cvt01(araw[cur][kk][0][0].x, araw[cur][kk][0][0].y);
            unsigned a1 = cvt01(araw[cur][kk][1][0].x, araw[cur][kk][1][0].y);
            unsigned a2 = cvt01(araw[cur][kk][0][1].x, araw[cur][kk][0][1].y);
            unsigned a3 = cvt01(araw[cur][kk][1][1].x, araw[cur][kk][1][1].y);
            unsigned b[10][2];
#pragma unroll
            for (int p = 0; p < 5; ++p) {
                int row = p * 16 + (lane & 7) + (((lane >> 4) & 1) << 3);
                int u   = 2 * kk + ((lane >> 3) & 1);
                unsigned ad = (unsigned)__cvta_generic_to_shared(
                    &Bs[cur][row * 64 + ((u ^ ((row >> 1) & 3)) * 16)]);
                asm volatile("ldmatrix.sync.aligned.m8n8.x4.shared.b16 {%0,%1,%2,%3}, [%4];"
                             : "=r"(b[2 * p][0]), "=r"(b[2 * p][1]),
                               "=r"(b[2 * p + 1][0]), "=r"(b[2 * p + 1][1]) : "r"(ad));
            }
#pragma unroll
            for (int nf = 0; nf < 10; ++nf)
                asm volatile(
                    "mma.sync.aligned.m16n8k16.row.col.f32.bf16.bf16.f32 "
                    "{%0,%1,%2,%3}, {%4,%5,%6,%7}, {%8,%9}, {%0,%1,%2,%3};"
                    : "+f"(c[nf][0]), "+f"(c[nf][1]), "+f"(c[nf][2]), "+f"(c[nf][3])
                    : "r"(a0), "r"(a1), "r"(a2), "r"(a3),
                      "r"(b[nf][0]), "r"(b[nf][1]));
        }
        __syncthreads();   // all warps done with Bs[cur] before refill
        if (ch + 2 < NCH) PREFETCH_B(cur, kbase + (ch + 2) * KC);
    }

    // store partial tile (deterministic split buffer, no atomics)
    size_t base = (size_t)ks * N_NODES * NS;
    int gc = tg * 2;
#pragma unroll
    for (int nf = 0; nf < 10; ++nf) {
        int n0 = nf * 8 + gc;
        *(float2*)&d_part[base + (size_t)rowA * NS + n0]       = make_float2(c[nf][0], c[nf][1]);
        *(float2*)&d_part[base + (size_t)(rowA + 8) * NS + n0] = make_float2(c[nf][2], c[nf][3]);
    }
#undef PREFETCH_B
#undef LOAD_A
}

// ---------------- K3: reduce splits, /deg, @Wp^T + bp, residual, LayerNorm ----------------
__global__ __launch_bounds__(256) void k3_epilogue(const float* __restrict__ x,
                                                   const float* __restrict__ bp,
                                                   const float* __restrict__ gamma,
                                                   const float* __restrict__ beta,
                                                   float* __restrict__ out) {
    __shared__ float nb[8][80];
    __shared__ float degs[8];
    __shared__ float red[8][16];
    __shared__ float stats[16];
    int tid = threadIdx.x;
    int i0  = blockIdx.x * 8;

#pragma unroll
    for (int it = 0; it < 3; ++it) {
        int idx = it * 256 + tid;
        if (idx < 640) {
            int nd = idx / 80, t = idx - nd * 80;
            size_t off = (size_t)(i0 + nd) * NS + t;
            float s = 0.f;
#pragma unroll
            for (int ks = 0; ks < KSPLIT; ++ks)
                s += d_part[(size_t)ks * N_NODES * NS + off];
            nb[nd][t] = s;
        }
    }
    __syncthreads();
    if (tid < 8) degs[tid] = nb[tid][64];     // ones-column = degree
    __syncthreads();
#pragma unroll
    for (int it = 0; it < 2; ++it) {
        int idx = it * 256 + tid;
        int nd = idx >> 6, t = idx & 63;
        float d = degs[nd];
        nb[nd][t] = (d > 0.5f) ? nb[nd][t] * (1.0f / d)
                               : d_hsum[t] * (1.0f / 8192.0f);  // uniform fallback
    }
    __syncthreads();

    int f = tid;
    float acc[8];
#pragma unroll
    for (int nd = 0; nd < 8; ++nd) acc[nd] = 0.f;
#pragma unroll 8
    for (int t = 0; t < 64; ++t) {
        float wv = d_WpT[t * 256 + f];
#pragma unroll
        for (int nd = 0; nd < 8; ++nd) acc[nd] += nb[nd][t] * wv;
    }
    float bpf = bp[f];
    float y[8], s1[8], s2[8];
#pragma unroll
    for (int nd = 0; nd < 8; ++nd) {
        y[nd]  = x[(size_t)(i0 + nd) * 256 + f] + acc[nd] + bpf;
        s1[nd] = y[nd];
        s2[nd] = y[nd] * y[nd];
    }
#pragma unroll
    for (int off = 16; off; off >>= 1)
#pragma unroll
        for (int nd = 0; nd < 8; ++nd) {
            s1[nd] += __shfl_xor_sync(0xffffffffu, s1[nd], off);
            s2[nd] += __shfl_xor_sync(0xffffffffu, s2[nd], off);
        }
    int lane = tid & 31, warp = tid >> 5;
    if (lane == 0) {
#pragma unroll
        for (int nd = 0; nd < 8; ++nd) {
            red[warp][nd * 2]     = s1[nd];
            red[warp][nd * 2 + 1] = s2[nd];
        }
    }
    __syncthreads();
    if (tid < 16) {
        float tot = 0.f;
#pragma unroll
        for (int w = 0; w < 8; ++w) tot += red[w][tid];
        stats[tid] = tot;
    }
    __syncthreads();
    float g = gamma[f], bb = beta[f];
#pragma unroll
    for (int nd = 0; nd < 8; ++nd) {
        float mu  = stats[nd * 2] * (1.0f / 256.0f);
        float var = stats[nd * 2 + 1] * (1.0f / 256.0f) - mu * mu;
        out[(size_t)(i0 + nd) * 256 + f] = g * (y[nd] - mu) * rsqrtf(var + 1e-5f) + bb;
    }
}

// ---------------- launch ----------------
extern "C" void kernel_launch(void* const* d_in, const int* in_sizes, int n_in,
                              void* d_out, int out_size) {
    const float* x     = (const float*)d_in[0];
    const int*   adj   = (const int*)  d_in[1];
    const float* Wt    = (const float*)d_in[2];
    const float* bt    = (const float*)d_in[3];
    // d_in[4]=Wa, d_in[5]=ba provably unused (row-constant score -> degenerate softmax)
    const float* Wp    = (const float*)d_in[6];
    const float* bp    = (const float*)d_in[7];
    const float* gamma = (const float*)d_in[8];
    const float* beta  = (const float*)d_in[9];
    float* out = (float*)d_out;

    k0_prep<<<640, 256>>>(Wt, Wp);
    k1_feat<<<128, 256>>>(x, bt);
    k1b_hsum<<<64, 256>>>();
    k2_spmm<<<dim3(N_NODES / MT, KSPLIT), 128>>>(adj);
    k3_epilogue<<<1024, 256>>>(x, bp, gamma, beta, out);
}

// round 11
// speedup vs baseline: 1.4732x; 1.4732x over previous
#include <cuda_runtime.h>
#include <cuda_bf16.h>
#include <cstdint>

#define N_NODES 8192
#define F_DIM   256
#define H_DIM   64
#define NS      80      // padded B rows: 64 h-feats + 1 ones (deg) + 15 zero
#define KSPLIT  4
#define MT      64      // M rows per CTA (4 warps x 16)
#define KC      32      // K chunk

// ---------------- scratch (static device globals; no allocation) ----------------
__device__ __align__(16) float          d_WtT[F_DIM * H_DIM];       // [256][64]
__device__ __align__(16) float          d_WpT[H_DIM * F_DIM];       // [64][256]
__device__ __align__(16) __nv_bfloat16  d_hT[NS * N_NODES];         // [80][8192]
__device__ __align__(16) float          d_part[(size_t)KSPLIT * N_NODES * NS]; // ~10.5MB
__device__ __align__(16) float          d_hsum[H_DIM];

// ---------------- K0: transpose weights, fill padded hT rows ----------------
__global__ void k0_prep(const float* __restrict__ Wt, const float* __restrict__ Wp) {
    int i = blockIdx.x * blockDim.x + threadIdx.x;
    if (i < 16384) {
        int f = i >> 6, t = i & 63;
        d_WtT[i] = Wt[t * 256 + f];
    } else if (i < 32768) {
        int j = i - 16384;
        int t = j >> 8, f = j & 255;
        d_WpT[j] = Wp[f * 64 + t];
    } else if (i < 32768 + 16 * 8192) {
        int j = i - 32768;
        int r = j >> 13, c = j & 8191;              // rows 64..79
        d_hT[(64 + r) * 8192 + c] = (r == 0) ? __float2bfloat16(1.0f)
                                             : __float2bfloat16(0.0f);
    }
}

// ---------------- K1: h = x@Wt^T + bt, write transposed bf16 hT[t][node] ----------------
__global__ __launch_bounds__(256) void k1_feat(const float* __restrict__ x,
                                               const float* __restrict__ bt) {
    __shared__ float xs[64 * 65];
    __shared__ float ws[64 * 64];
    int tid = threadIdx.x;
    int i0  = blockIdx.x * 64;
    int t   = tid & 63, grp = tid >> 6;
    float acc[16];
#pragma unroll
    for (int j = 0; j < 16; ++j) acc[j] = 0.f;

    for (int c = 0; c < 4; ++c) {
        __syncthreads();
#pragma unroll
        for (int it = 0; it < 16; ++it) {
            int idx = it * 256 + tid;
            int n = idx >> 6, f = idx & 63;
            xs[n * 65 + f] = x[(size_t)(i0 + n) * 256 + c * 64 + f];
            ws[idx]        = d_WtT[c * 4096 + idx];
        }
        __syncthreads();
#pragma unroll 8
        for (int f = 0; f < 64; ++f) {
            float wv = ws[f * 64 + t];
#pragma unroll
            for (int j = 0; j < 16; ++j)
                acc[j] += xs[(grp * 16 + j) * 65 + f] * wv;
        }
    }
    float bv = bt[t];
#pragma unroll
    for (int j = 0; j < 16; ++j) {
        int node = i0 + grp * 16 + j;
        d_hT[t * 8192 + node] = __float2bfloat16(acc[j] + bv);
    }
}

// ---------------- K1b: column sums of h (deg==0 fallback) ----------------
__global__ void k1b_hsum() {
    int t = blockIdx.x, tid = threadIdx.x;
    float s = 0.f;
    for (int i = tid; i < 8192; i += 256)
        s += __bfloat162float(d_hT[t * 8192 + i]);
#pragma unroll
    for (int off = 16; off; off >>= 1) s += __shfl_xor_sync(0xffffffffu, s, off);
    __shared__ float red[8];
    if ((tid & 31) == 0) red[tid >> 5] = s;
    __syncthreads();
    if (tid == 0) {
        float tot = 0.f;
        for (int w = 0; w < 8; ++w) tot += red[w];
        d_hsum[t] = tot;
    }
}

// ---------------- K2: SpMM, 2-stage pipelined adj stream (compile-time stages) ----------------
__device__ __forceinline__ void cp16(unsigned dst, const void* src) {
    asm volatile("cp.async.cg.shared.global [%0], [%1], 16;\n" :: "r"(dst), "l"(src));
}
__device__ __forceinline__ unsigned cvt01(int lo, int hi) {
    // {0,1} ints -> packed bf16x2 {0, 1.0f}
    return (unsigned)lo * 0x3F80u + (unsigned)hi * 0x3F800000u;
}

__global__ __launch_bounds__(128, 4) void k2_spmm(const int* __restrict__ adj) {
    // B stage: 80 rows x 32 k (64B/row), XOR swizzle u^=(r>>1)&3 (conflict-free)
    __shared__ __align__(16) unsigned char Bs[2][NS * 64];
    int tid  = threadIdx.x;
    int lane = tid & 31, mw = tid >> 5;
    int i0    = blockIdx.x * MT;
    int ks    = blockIdx.y;
    int kbase = ks * (N_NODES / KSPLIT);
    const int NCH = (N_NODES / KSPLIT) / KC;   // 64 (even)

    float c[10][4];
#pragma unroll
    for (int nf = 0; nf < 10; ++nf)
#pragma unroll
        for (int q = 0; q < 4; ++q) c[nf][q] = 0.f;

    // B prefetch: 320 16B units per stage
#define PREFETCH_B(stage, kc0)                                                        \
    {                                                                                 \
        _Pragma("unroll")                                                             \
        for (int i = 0; i < 3; ++i) {                                                 \
            int idx = tid + i * 128;                                                  \
            if (idx < 320) {                                                          \
                int r = idx >> 2, u = idx & 3;                                        \
                const unsigned char* src = (const unsigned char*)d_hT +               \
                    (size_t)r * (N_NODES * 2) + (size_t)(kc0) * 2 + u * 16;           \
                unsigned dst = (unsigned)__cvta_generic_to_shared(                    \
                    &Bs[stage][r * 64 + ((u ^ ((r >> 1) & 3)) * 16)]);                \
                cp16(dst, src);                                                       \
            }                                                                         \
        }                                                                             \
        asm volatile("cp.async.commit_group;\n");                                     \
    }

    int g = lane >> 2, tg = lane & 3;
    int rowA = i0 + mw * 16 + g;
    const int* aptr0 = adj + (size_t)rowA * N_NODES + kbase + tg * 2;
    const int* aptr1 = aptr0 + (size_t)8 * N_NODES;

    // two register stages, ALWAYS indexed by compile-time literals
    int2 araw0[2][2][2], araw1[2][2][2];   // [kk][rowsel][khalf]

#define LOAD_A(stage, coff)                                                           \
    {                                                                                 \
        _Pragma("unroll")                                                             \
        for (int kk = 0; kk < 2; ++kk)                                                \
        {                                                                             \
            _Pragma("unroll")                                                         \
            for (int h = 0; h < 2; ++h) {                                             \
                araw##stage[kk][0][h] = *(const int2*)(aptr0 + (coff) + kk * 16 + h * 8); \
                araw##stage[kk][1][h] = *(const int2*)(aptr1 + (coff) + kk * 16 + h * 8); \
            }                                                                         \
        }                                                                             \
    }

#define MMA_PHASE(stage)                                                              \
    {                                                                                 \
        _Pragma("unroll")                                                             \
        for (int kk = 0; kk < 2; ++kk) {                                              \
            unsigned a0 = cvt01(araw##stage[kk][0][0].x, araw##stage[kk][0][0].y);    \
            unsigned a1 = cvt01(araw##stage[kk][1][0].x, araw##stage[kk][1][0].y);    \
            unsigned a2 = cvt01(araw##stage[kk][0][1].x, araw##stage[kk][0][1].y);    \
            unsigned a3 = cvt01(araw##stage[kk][1][1].x, araw##stage[kk][1][1].y);    \
            unsigned b[10][2];                                                        \
            _Pragma("unroll")                                                         \
            for (int p = 0; p < 5; ++p) {                                             \
                int row = p * 16 + (lane & 7) + (((lane >> 4) & 1) << 3);             \
                int u   = 2 * kk + ((lane >> 3) & 1);                                 \
                unsigned ad = (unsigned)__cvta_generic_to_shared(                     \
                    &Bs[stage][row * 64 + ((u ^ ((row >> 1) & 3)) * 16)]);            \
                asm volatile("ldmatrix.sync.aligned.m8n8.x4.shared.b16 {%0,%1,%2,%3}, [%4];" \
                             : "=r"(b[2 * p][0]), "=r"(b[2 * p][1]),                  \
                               "=r"(b[2 * p + 1][0]), "=r"(b[2 * p + 1][1]) : "r"(ad)); \
            }                                                                         \
            _Pragma("unroll")                                                         \
            for (int nf = 0; nf < 10; ++nf)                                           \
                asm volatile(                                                         \
                    "mma.sync.aligned.m16n8k16.row.col.f32.bf16.bf16.f32 "            \
                    "{%0,%1,%2,%3}, {%4,%5,%6,%7}, {%8,%9}, {%0,%1,%2,%3};"           \
                    : "+f"(c[nf][0]), "+f"(c[nf][1]), "+f"(c[nf][2]), "+f"(c[nf][3])  \
                    : "r"(a0), "r"(a1), "r"(a2), "r"(a3),                             \
                      "r"(b[nf][0]), "r"(b[nf][1]));                                  \
        }                                                                             \
    }

    PREFETCH_B(0, kbase);
    LOAD_A(0, 0);
    PREFETCH_B(1, kbase + KC);

    for (int ch2 = 0; ch2 < NCH; ch2 += 2) {
        // ---- stage 0 : consumes chunk ch2 ----
        if (ch2 + 2 < NCH) { asm volatile("cp.async.wait_group 1;\n"); }
        else               { asm volatile("cp.async.wait_group 1;\n"); } // B[ch2+1] newest
        __syncthreads();
        // issue chunk ch2+1's adjacency loads before consuming chunk ch2
        LOAD_A(1, (ch2 + 1) * KC);
        MMA_PHASE(0);
        __syncthreads();
        if (ch2 + 2 < NCH) PREFETCH_B(0, kbase + (ch2 + 2) * KC);

        // ---- stage 1 : consumes chunk ch2+1 ----
        if (ch2 + 2 < NCH) { asm volatile("cp.async.wait_group 1;\n"); }
        else               { asm volatile("cp.async.wait_group 0;\n"); }
        __syncthreads();
        if (ch2 + 2 < NCH) LOAD_A(0, (ch2 + 2) * KC);
        MMA_PHASE(1);
        __syncthreads();
        if (ch2 + 3 < NCH) PREFETCH_B(1, kbase + (ch2 + 3) * KC);
    }

    // store partial tile (deterministic split buffer, no atomics)
    size_t base = (size_t)ks * N_NODES * NS;
    int gc = tg * 2;
#pragma unroll
    for (int nf = 0; nf < 10; ++nf) {
        int n0 = nf * 8 + gc;
        *(float2*)&d_part[base + (size_t)rowA * NS + n0]       = make_float2(c[nf][0], c[nf][1]);
        *(float2*)&d_part[base + (size_t)(rowA + 8) * NS + n0] = make_float2(c[nf][2], c[nf][3]);
    }
#undef PREFETCH_B
#undef LOAD_A
#undef MMA_PHASE
}

// ---------------- K3: reduce splits, /deg, @Wp^T + bp, residual, LayerNorm ----------------
__global__ __launch_bounds__(256) void k3_epilogue(const float* __restrict__ x,
                                                   const float* __restrict__ bp,
                                                   const float* __restrict__ gamma,
                                                   const float* __restrict__ beta,
                                                   float* __restrict__ out) {
    __shared__ float nb[8][80];
    __shared__ float degs[8];
    __shared__ float red[8][16];
    __shared__ float stats[16];
    int tid = threadIdx.x;
    int i0  = blockIdx.x * 8;

#pragma unroll
    for (int it = 0; it < 3; ++it) {
        int idx = it * 256 + tid;
        if (idx < 640) {
            int nd = idx / 80, t = idx - nd * 80;
            size_t off = (size_t)(i0 + nd) * NS + t;
            float s = 0.f;
#pragma unroll
            for (int ks = 0; ks < KSPLIT; ++ks)
                s += d_part[(size_t)ks * N_NODES * NS + off];
            nb[nd][t] = s;
        }
    }
    __syncthreads();
    if (tid < 8) degs[tid] = nb[tid][64];     // ones-column = degree
    __syncthreads();
#pragma unroll
    for (int it = 0; it < 2; ++it) {
        int idx = it * 256 + tid;
        int nd = idx >> 6, t = idx & 63;
        float d = degs[nd];
        nb[nd][t] = (d > 0.5f) ? nb[nd][t] * (1.0f / d)
                               : d_hsum[t] * (1.0f / 8192.0f);  // uniform fallback
    }
    __syncthreads();

    int f = tid;
    float acc[8];
#pragma unroll
    for (int nd = 0; nd < 8; ++nd) acc[nd] = 0.f;
#pragma unroll 8
    for (int t = 0; t < 64; ++t) {
        float wv = d_WpT[t * 256 + f];
#pragma unroll
        for (int nd = 0; nd < 8; ++nd) acc[nd] += nb[nd][t] * wv;
    }
    float bpf = bp[f];
    float y[8], s1[8], s2[8];
#pragma unroll
    for (int nd = 0; nd < 8; ++nd) {
        y[nd]  = x[(size_t)(i0 + nd) * 256 + f] + acc[nd] + bpf;
        s1[nd] = y[nd];
        s2[nd] = y[nd] * y[nd];
    }
#pragma unroll
    for (int off = 16; off; off >>= 1)
#pragma unroll
        for (int nd = 0; nd < 8; ++nd) {
            s1[nd] += __shfl_xor_sync(0xffffffffu, s1[nd], off);
            s2[nd] += __shfl_xor_sync(0xffffffffu, s2[nd], off);
        }
    int lane = tid & 31, warp = tid >> 5;
    if (lane == 0) {
#pragma unroll
        for (int nd = 0; nd < 8; ++nd) {
            red[warp][nd * 2]     = s1[nd];
            red[warp][nd * 2 + 1] = s2[nd];
        }
    }
    __syncthreads();
    if (tid < 16) {
        float tot = 0.f;
#pragma unroll
        for (int w = 0; w < 8; ++w) tot += red[w][tid];
        stats[tid] = tot;
    }
    __syncthreads();
    float g = gamma[f], bb = beta[f];
#pragma unroll
    for (int nd = 0; nd < 8; ++nd) {
        float mu  = stats[nd * 2] * (1.0f / 256.0f);
        float var = stats[nd * 2 + 1] * (1.0f / 256.0f) - mu * mu;
        out[(size_t)(i0 + nd) * 256 + f] = g * (y[nd] - mu) * rsqrtf(var + 1e-5f) + bb;
    }
}

// ---------------- launch ----------------
extern "C" void kernel_launch(void* const* d_in, const int* in_sizes, int n_in,
                              void* d_out, int out_size) {
    const float* x     = (const float*)d_in[0];
    const int*   adj   = (const int*)  d_in[1];
    const float* Wt    = (const float*)d_in[2];
    const float* bt    = (const float*)d_in[3];
    // d_in[4]=Wa, d_in[5]=ba provably unused (row-constant score -> degenerate softmax)
    const float* Wp    = (const float*)d_in[6];
    const float* bp    = (const float*)d_in[7];
    const float* gamma = (const float*)d_in[8];
    const float* beta  = (const float*)d_in[9];
    float* out = (float*)d_out;

    k0_prep<<<640, 256>>>(Wt, Wp);
    k1_feat<<<128, 256>>>(x, bt);
    k1b_hsum<<<64, 256>>>();
    k2_spmm<<<dim3(N_NODES / MT, KSPLIT), 128>>>(adj);
    k3_epilogue<<<1024, 256>>>(x, bp, gamma, beta, out);
}

// round 13
// speedup vs baseline: 1.5451x; 1.0489x over previous
#include <cuda_runtime.h>
#include <cuda_bf16.h>
#include <cstdint>

#define N_NODES 8192
#define F_DIM   256
#define H_DIM   64
#define NS      80      // padded B rows: 64 h-feats + 1 ones (deg) + 15 zero
#define KSPLIT  4
#define MT      64      // M rows per CTA (4 warps x 16)
#define KC      32      // K chunk

// ---------------- scratch (static device globals; no allocation) ----------------
__device__ __align__(16) float          d_WtT[F_DIM * H_DIM];       // [256][64]
__device__ __align__(16) float          d_WpT[H_DIM * F_DIM];       // [64][256]
__device__ __align__(16) __nv_bfloat16  d_hT[NS * N_NODES];         // [80][8192], k-permuted per 16-block
__device__ __align__(16) float          d_part[(size_t)KSPLIT * N_NODES * NS]; // ~10.5MB
__device__ __align__(16) float          d_hsum[H_DIM];

// ---------------- K0: transpose weights, fill padded hT rows ----------------
__global__ void k0_prep(const float* __restrict__ Wt, const float* __restrict__ Wp) {
    int i = blockIdx.x * blockDim.x + threadIdx.x;
    if (i < 16384) {
        int f = i >> 6, t = i & 63;
        d_WtT[i] = Wt[t * 256 + f];
    } else if (i < 32768) {
        int j = i - 16384;
        int t = j >> 8, f = j & 255;
        d_WpT[j] = Wp[f * 64 + t];
    } else if (i < 32768 + 16 * 8192) {
        int j = i - 32768;
        int r = j >> 13, c = j & 8191;              // rows 64..79 (constant: perm-invariant)
        d_hT[(64 + r) * 8192 + c] = (r == 0) ? __float2bfloat16(1.0f)
                                             : __float2bfloat16(0.0f);
    }
}

// node permutation within each 16-block: lets A use LDG.128 of 4 consecutive k
// while B (via standard ldmatrix pickup) sees the same k order.
__device__ __forceinline__ int kperm(int v) {
    // v in 0..15 ; q=v>>1 pair, o=v&1 ; p=(q>>1)+4*(q&1) ; v'=2p+o
    return ((v >> 2) << 1) | ((v & 2) << 2) | (v & 1);
}

// ---------------- K1: h = x@Wt^T + bt, write transposed bf16 hT[t][perm(node)] ----------------
__global__ __launch_bounds__(256) void k1_feat(const float* __restrict__ x,
                                               const float* __restrict__ bt) {
    __shared__ float xs[64 * 65];
    __shared__ float ws[64 * 64];
    int tid = threadIdx.x;
    int i0  = blockIdx.x * 64;
    int t   = tid & 63, grp = tid >> 6;
    float acc[16];
#pragma unroll
    for (int j = 0; j < 16; ++j) acc[j] = 0.f;

    for (int c = 0; c < 4; ++c) {
        __syncthreads();
#pragma unroll
        for (int it = 0; it < 16; ++it) {
            int idx = it * 256 + tid;
            int n = idx >> 6, f = idx & 63;
            xs[n * 65 + f] = x[(size_t)(i0 + n) * 256 + c * 64 + f];
            ws[idx]        = d_WtT[c * 4096 + idx];
        }
        __syncthreads();
#pragma unroll 8
        for (int f = 0; f < 64; ++f) {
            float wv = ws[f * 64 + t];
#pragma unroll
            for (int j = 0; j < 16; ++j)
                acc[j] += xs[(grp * 16 + j) * 65 + f] * wv;
        }
    }
    float bv = bt[t];
#pragma unroll
    for (int j = 0; j < 16; ++j) {
        int node = i0 + grp * 16 + j;
        int nperm = (node & ~15) | kperm(node & 15);
        d_hT[t * 8192 + nperm] = __float2bfloat16(acc[j] + bv);
    }
}

// ---------------- K1b: column sums of h (deg==0 fallback; perm-invariant) ----------------
__global__ void k1b_hsum() {
    int t = blockIdx.x, tid = threadIdx.x;
    float s = 0.f;
    for (int i = tid; i < 8192; i += 256)
        s += __bfloat162float(d_hT[t * 8192 + i]);
#pragma unroll
    for (int off = 16; off; off >>= 1) s += __shfl_xor_sync(0xffffffffu, s, off);
    __shared__ float red[8];
    if ((tid & 31) == 0) red[tid >> 5] = s;
    __syncthreads();
    if (tid == 0) {
        float tot = 0.f;
        for (int w = 0; w < 8; ++w) tot += red[w];
        d_hsum[t] = tot;
    }
}

// ---------------- K2: SpMM, LDG.128 adj stream + 2-stage pipeline ----------------
__device__ __forceinline__ void cp16(unsigned dst, const void* src) {
    asm volatile("cp.async.cg.shared.global [%0], [%1], 16;\n" :: "r"(dst), "l"(src));
}
__device__ __forceinline__ unsigned cvt01(int lo, int hi) {
    // {0,1} ints -> packed bf16x2 {0, 1.0f}
    return (unsigned)lo * 0x3F80u + (unsigned)hi * 0x3F800000u;
}

__global__ __launch_bounds__(128, 4) void k2_spmm(const int* __restrict__ adj) {
    // B stage: 80 rows x 32 k (64B/row), XOR swizzle u^=(r>>1)&3 (conflict-free)
    __shared__ __align__(16) unsigned char Bs[2][NS * 64];
    int tid  = threadIdx.x;
    int lane = tid & 31, mw = tid >> 5;
    int i0    = blockIdx.x * MT;
    int ks    = blockIdx.y;
    int kbase = ks * (N_NODES / KSPLIT);
    const int NCH = (N_NODES / KSPLIT) / KC;   // 64 (even)

    float c[10][4];
#pragma unroll
    for (int nf = 0; nf < 10; ++nf)
#pragma unroll
        for (int q = 0; q < 4; ++q) c[nf][q] = 0.f;

#define PREFETCH_B(stage, kc0)                                                        \
    {                                                                                 \
        _Pragma("unroll")                                                             \
        for (int i = 0; i < 3; ++i) {                                                 \
            int idx = tid + i * 128;                                                  \
            if (idx < 320) {                                                          \
                int r = idx >> 2, u = idx & 3;                                        \
                const unsigned char* src = (const unsigned char*)d_hT +               \
                    (size_t)r * (N_NODES * 2) + (size_t)(kc0) * 2 + u * 16;           \
                unsigned dst = (unsigned)__cvta_generic_to_shared(                    \
                    &Bs[stage][r * 64 + ((u ^ ((r >> 1) & 3)) * 16)]);                \
                cp16(dst, src);                                                       \
            }                                                                         \
        }                                                                             \
        asm volatile("cp.async.commit_group;\n");                                     \
    }

    int g = lane >> 2, tg = lane & 3;
    int rowA = i0 + mw * 16 + g;
    // LDG.128: thread tg owns k = 4tg..4tg+3 of each k16 step (permuted contraction)
    const int* aptr0 = adj + (size_t)rowA * N_NODES + kbase + tg * 4;
    const int* aptr1 = aptr0 + (size_t)8 * N_NODES;

    // two register stages, ALWAYS indexed by compile-time literals
    int4 araw0[2][2], araw1[2][2];   // [kk][rowsel]

#define LOAD_A(stage, coff)                                                           \
    {                                                                                 \
        _Pragma("unroll")                                                             \
        for (int kk = 0; kk < 2; ++kk) {                                              \
            araw##stage[kk][0] = *(const int4*)(aptr0 + (coff) + kk * 16);            \
            araw##stage[kk][1] = *(const int4*)(aptr1 + (coff) + kk * 16);            \
        }                                                                             \
    }

#define MMA_PHASE(stage)                                                              \
    {                                                                                 \
        _Pragma("unroll")                                                             \
        for (int kk = 0; kk < 2; ++kk) {                                              \
            unsigned a0 = cvt01(araw##stage[kk][0].x, araw##stage[kk][0].y);          \
            unsigned a1 = cvt01(araw##stage[kk][1].x, araw##stage[kk][1].y);          \
            unsigned a2 = cvt01(araw##stage[kk][0].z, araw##stage[kk][0].w);          \
            unsigned a3 = cvt01(araw##stage[kk][1].z, araw##stage[kk][1].w);          \
            unsigned b[10][2];                                                        \
            _Pragma("unroll")                                                         \
            for (int p = 0; p < 5; ++p) {                                             \
                int row = p * 16 + (lane & 7) + (((lane >> 4) & 1) << 3);             \
                int u   = 2 * kk + ((lane >> 3) & 1);                                 \
                unsigned ad = (unsigned)__cvta_generic_to_shared(                     \
                    &Bs[stage][row * 64 + ((u ^ ((row >> 1) & 3)) * 16)]);            \
                asm volatile("ldmatrix.sync.aligned.m8n8.x4.shared.b16 {%0,%1,%2,%3}, [%4];" \
                             : "=r"(b[2 * p][0]), "=r"(b[2 * p][1]),                  \
                               "=r"(b[2 * p + 1][0]), "=r"(b[2 * p + 1][1]) : "r"(ad)); \
            }                                                                         \
            _Pragma("unroll")                                                         \
            for (int nf = 0; nf < 10; ++nf)                                           \
                asm volatile(                                                         \
                    "mma.sync.aligned.m16n8k16.row.col.f32.bf16.bf16.f32 "            \
                    "{%0,%1,%2,%3}, {%4,%5,%6,%7}, {%8,%9}, {%0,%1,%2,%3};"           \
                    : "+f"(c[nf][0]), "+f"(c[nf][1]), "+f"(c[nf][2]), "+f"(c[nf][3])  \
                    : "r"(a0), "r"(a1), "r"(a2), "r"(a3),                             \
                      "r"(b[nf][0]), "r"(b[nf][1]));                                  \
        }                                                                             \
    }

    PREFETCH_B(0, kbase);
    LOAD_A(0, 0);
    PREFETCH_B(1, kbase + KC);

    for (int ch2 = 0; ch2 < NCH; ch2 += 2) {
        // ---- stage 0 : consumes chunk ch2 ----
        asm volatile("cp.async.wait_group 1;\n");
        __syncthreads();
        LOAD_A(1, (ch2 + 1) * KC);     // next chunk's adj loads before consuming current
        MMA_PHASE(0);
        __syncthreads();
        if (ch2 + 2 < NCH) PREFETCH_B(0, kbase + (ch2 + 2) * KC);

        // ---- stage 1 : consumes chunk ch2+1 ----
        if (ch2 + 2 < NCH) { asm volatile("cp.async.wait_group 1;\n"); }
        else               { asm volatile("cp.async.wait_group 0;\n"); }
        __syncthreads();
        if (ch2 + 2 < NCH) LOAD_A(0, (ch2 + 2) * KC);
        MMA_PHASE(1);
        __syncthreads();
        if (ch2 + 3 < NCH) PREFETCH_B(1, kbase + (ch2 + 3) * KC);
    }

    // store partial tile (deterministic split buffer, no atomics)
    size_t base = (size_t)ks * N_NODES * NS;
    int gc = tg * 2;
#pragma unroll
    for (int nf = 0; nf < 10; ++nf) {
        int n0 = nf * 8 + gc;
        *(float2*)&d_part[base + (size_t)rowA * NS + n0]       = make_float2(c[nf][0], c[nf][1]);
        *(float2*)&d_part[base + (size_t)(rowA + 8) * NS + n0] = make_float2(c[nf][2], c[nf][3]);
    }
#undef PREFETCH_B
#undef LOAD_A
#undef MMA_PHASE
}

// ---------------- K3: reduce splits, /deg, @Wp^T + bp, residual, LayerNorm ----------------
__global__ __launch_bounds__(256) void k3_epilogue(const float* __restrict__ x,
                                                   const float* __restrict__ bp,
                                                   const float* __restrict__ gamma,
                                                   const float* __restrict__ beta,
                                                   float* __restrict__ out) {
    __shared__ float nb[8][80];
    __shared__ float degs[8];
    __shared__ float red[8][16];
    __shared__ float stats[16];
    int tid = threadIdx.x;
    int i0  = blockIdx.x * 8;

#pragma unroll
    for (int it = 0; it < 3; ++it) {
        int idx = it * 256 + tid;
        if (idx < 640) {
            int nd = idx / 80, t = idx - nd * 80;
            size_t off = (size_t)(i0 + nd) * NS + t;
            float s = 0.f;
#pragma unroll
            for (int ks = 0; ks < KSPLIT; ++ks)
                s += d_part[(size_t)ks * N_NODES * NS + off];
            nb[nd][t] = s;
        }
    }
    __syncthreads();
    if (tid < 8) degs[tid] = nb[tid][64];     // ones-column = degree
    __syncthreads();
#pragma unroll
    for (int it = 0; it < 2; ++it) {
        int idx = it * 256 + tid;
        int nd = idx >> 6, t = idx & 63;
        float d = degs[nd];
        nb[nd][t] = (d > 0.5f) ? nb[nd][t] * (1.0f / d)
                               : d_hsum[t] * (1.0f / 8192.0f);  // uniform fallback
    }
    __syncthreads();

    int f = tid;
    float acc[8];
#pragma unroll
    for (int nd = 0; nd < 8; ++nd) acc[nd] = 0.f;
#pragma unroll 8
    for (int t = 0; t < 64; ++t) {
        float wv = d_WpT[t * 256 + f];
#pragma unroll
        for (int nd = 0; nd < 8; ++nd) acc[nd] += nb[nd][t] * wv;
    }
    float bpf = bp[f];
    float y[8], s1[8], s2[8];
#pragma unroll
    for (int nd = 0; nd < 8; ++nd) {
        y[nd]  = x[(size_t)(i0 + nd) * 256 + f] + acc[nd] + bpf;
        s1[nd] = y[nd];
        s2[nd] = y[nd] * y[nd];
    }
#pragma unroll
    for (int off = 16; off; off >>= 1)
#pragma unroll
        for (int nd = 0; nd < 8; ++nd) {
            s1[nd] += __shfl_xor_sync(0xffffffffu, s1[nd], off);
            s2[nd] += __shfl_xor_sync(0xffffffffu, s2[nd], off);
        }
    int lane = tid & 31, warp = tid >> 5;
    if (lane == 0) {
#pragma unroll
        for (int nd = 0; nd < 8; ++nd) {
            red[warp][nd * 2]     = s1[nd];
            red[warp][nd * 2 + 1] = s2[nd];
        }
    }
    __syncthreads();
    if (tid < 16) {
        float tot = 0.f;
#pragma unroll
        for (int w = 0; w < 8; ++w) tot += red[w][tid];
        stats[tid] = tot;
    }
    __syncthreads();
    float g = gamma[f], bb = beta[f];
#pragma unroll
    for (int nd = 0; nd < 8; ++nd) {
        float mu  = stats[nd * 2] * (1.0f / 256.0f);
        float var = stats[nd * 2 + 1] * (1.0f / 256.0f) - mu * mu;
        out[(size_t)(i0 + nd) * 256 + f] = g * (y[nd] - mu) * rsqrtf(var + 1e-5f) + bb;
    }
}

// ---------------- launch ----------------
extern "C" void kernel_launch(void* const* d_in, const int* in_sizes, int n_in,
                              void* d_out, int out_size) {
    const float* x     = (const float*)d_in[0];
    const int*   adj   = (const int*)  d_in[1];
    const float* Wt    = (const float*)d_in[2];
    const float* bt    = (const float*)d_in[3];
    // d_in[4]=Wa, d_in[5]=ba provably unused (row-constant score -> degenerate softmax)
    const float* Wp    = (const float*)d_in[6];
    const float* bp    = (const float*)d_in[7];
    const float* gamma = (const float*)d_in[8];
    const float* beta  = (const float*)d_in[9];
    float* out = (float*)d_out;

    k0_prep<<<640, 256>>>(Wt, Wp);
    k1_feat<<<128, 256>>>(x, bt);
    k1b_hsum<<<64, 256>>>();
    k2_spmm<<<dim3(N_NODES / MT, KSPLIT), 128>>>(adj);
    k3_epilogue<<<1024, 256>>>(x, bp, gamma, beta, out);
}